// round 2
// baseline (speedup 1.0000x reference)
#include <cuda_runtime.h>
#include <cuda_bf16.h>

// ---------------------------------------------------------------------------
// NNConv fused pipeline, tf32 mma.sync version.
//   K0: dtype-sniff edge_index, zero seg/cnt, pre-round w2 (+b2 row) to tf32
//   KA: h = relu(ea @ w1 + b1)  (fp32 cores) + degree counts
//   KB: msg GEMM  C[E,128] = T[E,16384] @ W2'   (tf32 HMMA, T built on the fly)
//       with fused atomic scatter into seg[]
//   KC: out = x + gelu(seg/max(cnt,1) + x@root + bias)
// ---------------------------------------------------------------------------

#define N_NODES 10000
#define N_EDGES 16384
#define DD      128
#define W2N     (128 * 16384)   // 2,097,152

// scratch (device globals: no allocation allowed)
__device__ float g_h[N_EDGES * DD];          // 8 MB
__device__ float g_w2t[(128 + 1) * 16384];   // w2 (tf32-rounded) + b2 row
__device__ float g_seg[N_NODES * DD];        // 5 MB
__device__ int   g_cnt[N_NODES];
__device__ int   g_is64;                     // edge_index dtype flag

// ---------------- helpers ----------------

__device__ __forceinline__ float tf32r(float f) {
    unsigned u;
    asm("cvt.rna.tf32.f32 %0, %1;" : "=r"(u) : "f"(f));
    return __uint_as_float(u);
}
__device__ __forceinline__ unsigned f2t(float f) {
    unsigned u;
    asm("cvt.rna.tf32.f32 %0, %1;" : "=r"(u) : "f"(f));
    return u;
}

// robust edge_index decode (int32 under default JAX config; int64 if x64 on)
__device__ __forceinline__ int load_idx(const void* ei, int pos) {
    if (g_is64) return (int)((const long long*)ei)[pos];
    return ((const int*)ei)[pos];
}

#define MMA_TF32(C0, C1, C2, C3, A0, A1, A2, A3, B0, B1)                        \
    asm volatile(                                                               \
        "mma.sync.aligned.m16n8k8.row.col.f32.tf32.tf32.f32 "                   \
        "{%0,%1,%2,%3}, {%4,%5,%6,%7}, {%8,%9}, {%0,%1,%2,%3};\n"               \
        : "+f"(C0), "+f"(C1), "+f"(C2), "+f"(C3)                                \
        : "r"(A0), "r"(A1), "r"(A2), "r"(A3), "r"(B0), "r"(B1))

__device__ __forceinline__ void cp_async16(void* smem_dst, const void* gsrc) {
    unsigned saddr = (unsigned)__cvta_generic_to_shared(smem_dst);
    asm volatile("cp.async.cg.shared.global [%0], [%1], 16;\n" ::"r"(saddr), "l"(gsrc));
}
#define CP_COMMIT() asm volatile("cp.async.commit_group;\n")
#define CP_WAIT1()  asm volatile("cp.async.wait_group 1;\n")

// ---------------- K0: init + dtype sniff ----------------

__global__ void k_init(const float* __restrict__ w2, const float* __restrict__ b2,
                       const void* __restrict__ ei) {
    // dtype sniff: if edge_index is int64 with values < 2^31, all odd 32-bit
    // words are zero. For int32 values in [0,10000), 2048 all-zero odd words
    // is impossible. One warp of block 0 decides.
    if (blockIdx.x == 0 && threadIdx.x < 32) {
        const int* e32 = (const int*)ei;
        int nz = 0;
        for (int i = threadIdx.x; i < 2048; i += 32) nz |= e32[2 * i + 1];
        unsigned any = __ballot_sync(0xffffffffu, nz != 0);
        if (threadIdx.x == 0) g_is64 = (any == 0u) ? 1 : 0;
    }
    int i = blockIdx.x * blockDim.x + threadIdx.x;
    int stride = gridDim.x * blockDim.x;
    for (int idx = i; idx < W2N + 16384; idx += stride)
        g_w2t[idx] = tf32r(idx < W2N ? w2[idx] : b2[idx - W2N]);
    for (int idx = i; idx < N_NODES * DD; idx += stride) g_seg[idx] = 0.0f;
    for (int idx = i; idx < N_NODES; idx += stride) g_cnt[idx] = 0;
}

// ---------------- KA: edge MLP layer 1 (+ degree counts) ----------------
// block: 256 threads, tile 64 edges x 128 k.  thread: 4 edges x 8 k.
// smem: eas[64][132], w1s[128][132]

#define SMEM_A ((64 * 132 + 128 * 132) * 4)

__global__ __launch_bounds__(256) void k_edge_mlp(
    const float* __restrict__ ea, const float* __restrict__ w1,
    const float* __restrict__ b1, const void* __restrict__ ei)
{
    extern __shared__ float smA[];
    float* eas = smA;             // [64][132]
    float* w1s = smA + 64 * 132;  // [128][132]
    const int tid = threadIdx.x;
    const int e0 = blockIdx.x * 64;

#pragma unroll
    for (int j = 0; j < 8; j++) {
        int idx = tid + j * 256;            // float4 index (64*32)
        int r = idx >> 5, c4 = idx & 31;
        *(float4*)(eas + r * 132 + c4 * 4) =
            *(const float4*)(ea + (e0 + r) * DD + c4 * 4);
    }
#pragma unroll
    for (int j = 0; j < 16; j++) {
        int idx = tid + j * 256;            // float4 index (128*32)
        int r = idx >> 5, c4 = idx & 31;
        *(float4*)(w1s + r * 132 + c4 * 4) = *(const float4*)(w1 + r * DD + c4 * 4);
    }
    __syncthreads();

    const int kq = tid & 15;   // 8 k values each
    const int eq = tid >> 4;   // 4 edges each
    float acc[4][8];
#pragma unroll
    for (int a = 0; a < 4; a++)
#pragma unroll
        for (int b = 0; b < 8; b++) acc[a][b] = 0.0f;

    for (int i = 0; i < DD; i++) {
        float4 wA = *(float4*)(w1s + i * 132 + kq * 8);
        float4 wB = *(float4*)(w1s + i * 132 + kq * 8 + 4);
#pragma unroll
        for (int je = 0; je < 4; je++) {
            float ev = eas[(eq * 4 + je) * 132 + i];
            acc[je][0] += ev * wA.x; acc[je][1] += ev * wA.y;
            acc[je][2] += ev * wA.z; acc[je][3] += ev * wA.w;
            acc[je][4] += ev * wB.x; acc[je][5] += ev * wB.y;
            acc[je][6] += ev * wB.z; acc[je][7] += ev * wB.w;
        }
    }

#pragma unroll
    for (int je = 0; je < 4; je++) {
        int e = e0 + eq * 4 + je;
#pragma unroll
        for (int jk = 0; jk < 8; jk++) {
            int k = kq * 8 + jk;
            g_h[e * DD + k] = fmaxf(acc[je][jk] + b1[k], 0.0f);
        }
    }
    if (tid < 64) {
        int dd = load_idx(ei, N_EDGES + e0 + tid);
        atomicAdd(&g_cnt[dd], 1);
    }
}

// ---------------- KB: big tf32 GEMM with on-the-fly A and fused scatter ----
// CTA tile: 128 edges x 128 outs. 8 warps: 4 (E) x 2 (O). warp: 32e x 64o.
// Chunks: 258 = 128 k * 2 i-halves + 2 virtual b2 chunks (h == 1).
// smem: Xs[128][132], Hs[128][132], Bs[2][64][136], src/dst[128]

#define SMEM_B ((128 * 132 + 128 * 132 + 2 * 64 * 136) * 4 + 256 * 4)

__global__ __launch_bounds__(256) void k_msg(
    const float* __restrict__ x, const void* __restrict__ ei)
{
    extern __shared__ char smraw[];
    float* Xs  = (float*)smraw;          // [128][132]
    float* Hs  = Xs + 128 * 132;         // [128][132]
    float* Bs  = Hs + 128 * 132;         // [2][64][136]
    int* s_src = (int*)(Bs + 2 * 64 * 136);
    int* s_dst = s_src + 128;

    const int tid = threadIdx.x;
    const int eBase = blockIdx.x * 128;

    if (tid < 128) {
        s_src[tid] = load_idx(ei, eBase + tid);
        s_dst[tid] = load_idx(ei, N_EDGES + eBase + tid);
    }
    __syncthreads();

    // gather x rows + h rows (float4, coalesced per-row)
#pragma unroll
    for (int j = 0; j < 16; j++) {
        int idx = tid + j * 256;          // float4 index among 128*32
        int r = idx >> 5, c4 = idx & 31;
        *(float4*)(Xs + r * 132 + c4 * 4) =
            *(const float4*)(x + s_src[r] * DD + c4 * 4);
        *(float4*)(Hs + r * 132 + c4 * 4) =
            *(const float4*)(g_h + (eBase + r) * DD + c4 * 4);
    }

    // prefetch first two B chunks
#pragma unroll
    for (int pc = 0; pc < 2; pc++) {
        const float* src = g_w2t + (pc >> 1) * 16384 + (pc & 1) * 8192;
        float* dst = Bs + (pc & 1) * 64 * 136;
#pragma unroll
        for (int j = 0; j < 8; j++) {
            int idx = tid + j * 256;      // float4 idx among 64*32
            int r = idx >> 5, c4 = idx & 31;
            cp_async16(dst + r * 136 + c4 * 4, src + r * 128 + c4 * 4);
        }
        CP_COMMIT();
    }
    __syncthreads();   // Xs/Hs visible

    const int w = tid >> 5, lane = tid & 31;
    const int wE = w >> 1, wO = w & 1;
    const int g = lane >> 2, tg = lane & 3;
    const int er0 = wE * 32;
    const int ob = wO * 64;

    const float* xr0 = Xs + (er0 + g) * 132;
    const float* xr1 = xr0 + 8 * 132;
    const float* xr2 = xr0 + 16 * 132;
    const float* xr3 = xr0 + 24 * 132;
    const float* hr0 = Hs + (er0 + g) * 132;
    const float* hr1 = hr0 + 8 * 132;
    const float* hr2 = hr0 + 16 * 132;
    const float* hr3 = hr0 + 24 * 132;

    float cacc[2][8][4];
#pragma unroll
    for (int a = 0; a < 2; a++)
#pragma unroll
        for (int b = 0; b < 8; b++)
#pragma unroll
            for (int q = 0; q < 4; q++) cacc[a][b][q] = 0.0f;

    const int NCH = 258;
    for (int ch = 0; ch < NCH; ch++) {
        CP_WAIT1();
        __syncthreads();
        const float* bsm = Bs + (ch & 1) * 64 * 136;
        const int k = ch >> 1;
        const int ihalf = (ch & 1) * 64;

        float h0, h1, h2, h3;
        if (k < 128) {
            h0 = hr0[k]; h1 = hr1[k]; h2 = hr2[k]; h3 = hr3[k];
        } else {
            h0 = h1 = h2 = h3 = 1.0f;   // b2 bilinear term
        }
        const int ib = ihalf + tg;

#pragma unroll
        for (int s = 0; s < 8; s++) {
            const int c0 = ib + s * 8, c1 = c0 + 4;
            unsigned A0 = f2t(h0 * xr0[c0]);
            unsigned A1 = f2t(h1 * xr1[c0]);
            unsigned A2 = f2t(h0 * xr0[c1]);
            unsigned A3 = f2t(h1 * xr1[c1]);
            unsigned A4 = f2t(h2 * xr2[c0]);
            unsigned A5 = f2t(h3 * xr3[c0]);
            unsigned A6 = f2t(h2 * xr2[c1]);
            unsigned A7 = f2t(h3 * xr3[c1]);
            const float* bp0 = bsm + (s * 8 + tg) * 136 + ob + g;
            const float* bp1 = bp0 + 4 * 136;
#pragma unroll
            for (int nt = 0; nt < 8; nt++) {
                unsigned B0 = __float_as_uint(bp0[nt * 8]);
                unsigned B1 = __float_as_uint(bp1[nt * 8]);
                MMA_TF32(cacc[0][nt][0], cacc[0][nt][1], cacc[0][nt][2], cacc[0][nt][3],
                         A0, A1, A2, A3, B0, B1);
                MMA_TF32(cacc[1][nt][0], cacc[1][nt][1], cacc[1][nt][2], cacc[1][nt][3],
                         A4, A5, A6, A7, B0, B1);
            }
        }
        __syncthreads();   // all warps done with Bs[ch&1] before overwrite
        if (ch + 2 < NCH) {
            int pc = ch + 2;
            const float* src = g_w2t + (pc >> 1) * 16384 + (pc & 1) * 8192;
            float* dst = Bs + (pc & 1) * 64 * 136;
#pragma unroll
            for (int j = 0; j < 8; j++) {
                int idx = tid + j * 256;
                int r = idx >> 5, c4 = idx & 31;
                cp_async16(dst + r * 136 + c4 * 4, src + r * 128 + c4 * 4);
            }
        }
        CP_COMMIT();   // empty groups at the tail keep wait-count arithmetic simple
    }

    // fused scatter: atomicAdd into seg
#pragma unroll
    for (int mt = 0; mt < 2; mt++) {
        int rl = er0 + mt * 16 + g;
        int d0 = s_dst[rl];
        int d1 = s_dst[rl + 8];
#pragma unroll
        for (int nt = 0; nt < 8; nt++) {
            int colb = ob + nt * 8 + tg * 2;
            atomicAdd(g_seg + d0 * DD + colb,     cacc[mt][nt][0]);
            atomicAdd(g_seg + d0 * DD + colb + 1, cacc[mt][nt][1]);
            atomicAdd(g_seg + d1 * DD + colb,     cacc[mt][nt][2]);
            atomicAdd(g_seg + d1 * DD + colb + 1, cacc[mt][nt][3]);
        }
    }
}

// ---------------- KC: mean + root transform + bias + gelu + residual -------
// block: 256 threads, tile 64 nodes x 128 outs. thread: 4 nodes x 8 outs.

#define SMEM_C ((64 * 132 + 128 * 132) * 4)

__global__ __launch_bounds__(256) void k_final(
    const float* __restrict__ x, const float* __restrict__ root,
    const float* __restrict__ bias, float* __restrict__ out)
{
    extern __shared__ float smC[];
    float* xs = smC;             // [64][132]
    float* rs = smC + 64 * 132;  // [128][132]
    const int tid = threadIdx.x;
    const int n0 = blockIdx.x * 64;

#pragma unroll
    for (int j = 0; j < 8; j++) {
        int idx = tid + j * 256;
        int r = idx >> 5, c4 = idx & 31;
        float4 v = make_float4(0.f, 0.f, 0.f, 0.f);
        if (n0 + r < N_NODES) v = *(const float4*)(x + (n0 + r) * DD + c4 * 4);
        *(float4*)(xs + r * 132 + c4 * 4) = v;
    }
#pragma unroll
    for (int j = 0; j < 16; j++) {
        int idx = tid + j * 256;
        int r = idx >> 5, c4 = idx & 31;
        *(float4*)(rs + r * 132 + c4 * 4) = *(const float4*)(root + r * DD + c4 * 4);
    }
    __syncthreads();

    const int oq = tid & 15;   // 8 outs each
    const int nq = tid >> 4;   // 4 nodes each
    float acc[4][8];
#pragma unroll
    for (int a = 0; a < 4; a++)
#pragma unroll
        for (int b = 0; b < 8; b++) acc[a][b] = 0.0f;

    for (int i = 0; i < DD; i++) {
        float4 rA = *(float4*)(rs + i * 132 + oq * 8);
        float4 rB = *(float4*)(rs + i * 132 + oq * 8 + 4);
#pragma unroll
        for (int jn = 0; jn < 4; jn++) {
            float xv = xs[(nq * 4 + jn) * 132 + i];
            acc[jn][0] += xv * rA.x; acc[jn][1] += xv * rA.y;
            acc[jn][2] += xv * rA.z; acc[jn][3] += xv * rA.w;
            acc[jn][4] += xv * rB.x; acc[jn][5] += xv * rB.y;
            acc[jn][6] += xv * rB.z; acc[jn][7] += xv * rB.w;
        }
    }

#pragma unroll
    for (int jn = 0; jn < 4; jn++) {
        int n = n0 + nq * 4 + jn;
        if (n < N_NODES) {
            float invc = 1.0f / fmaxf((float)g_cnt[n], 1.0f);
#pragma unroll
            for (int jo = 0; jo < 8; jo++) {
                int o = oq * 8 + jo;
                float v = acc[jn][jo] + bias[o] + g_seg[n * DD + o] * invc;
                float gl = 0.5f * v * (1.0f + erff(v * 0.70710678118654752f));
                out[n * DD + o] = xs[(nq * 4 + jn) * 132 + o] + gl;
            }
        }
    }
}

// ---------------- launch ----------------

extern "C" void kernel_launch(void* const* d_in, const int* in_sizes, int n_in,
                              void* d_out, int out_size) {
    const float* x    = (const float*)d_in[0];
    const void*  ei   = (const void*)d_in[1];
    const float* ea   = (const float*)d_in[2];
    const float* w1   = (const float*)d_in[3];
    const float* b1   = (const float*)d_in[4];
    const float* w2   = (const float*)d_in[5];
    const float* b2   = (const float*)d_in[6];
    const float* root = (const float*)d_in[7];
    const float* bias = (const float*)d_in[8];
    float*       out  = (float*)d_out;

    cudaFuncSetAttribute(k_edge_mlp, cudaFuncAttributeMaxDynamicSharedMemorySize, SMEM_A);
    cudaFuncSetAttribute(k_msg,      cudaFuncAttributeMaxDynamicSharedMemorySize, SMEM_B);
    cudaFuncSetAttribute(k_final,    cudaFuncAttributeMaxDynamicSharedMemorySize, SMEM_C);

    k_init<<<2048, 256>>>(w2, b2, ei);
    k_edge_mlp<<<N_EDGES / 64, 256, SMEM_A>>>(ea, w1, b1, ei);
    k_msg<<<N_EDGES / 128, 256, SMEM_B>>>(x, ei);
    k_final<<<(N_NODES + 63) / 64, 256, SMEM_C>>>(x, root, bias, out);
}

// round 8
// speedup vs baseline: 1.3758x; 1.3758x over previous
#include <cuda_runtime.h>
#include <cuda_fp16.h>
#include <cstdint>

// ---------------------------------------------------------------------------
// NNConv fused pipeline, fp16 mma.sync version (legacy tensor path; tcgen05 is
// unavailable: harness compiles PTX at .target sm_103 which rejects it).
//   K0: dtype-sniff edge_index, zero seg/cnt, w2 -> fp16 [k][ihalf][o][i64]
//       (+ b2 as virtual k=128 block)
//   KA: h = relu(ea @ w1 + b1) (fp32 cores) + degree counts
//   KB: msg GEMM C[E,128] = T[E,16512] @ W2'  via mma.sync.m16n8k16.f16
//       (T built on the fly: fp32 h*x, one rounding to fp16), fused scatter
//   KC: out = x + gelu(seg/max(cnt,1) + x@root + bias)
// ---------------------------------------------------------------------------

#define N_NODES 10000
#define N_EDGES 16384
#define DD      128
#define W2HN    ((DD + 1) * 16384)   // fp16 w2 blocks + b2 block

__device__ float  g_h[N_EDGES * DD];   // [e][k] row-major
__device__ __half g_w2h[W2HN];         // [k][ihalf][o][il]: k*16384+ih*8192+o*64+il
__device__ float  g_seg[N_NODES * DD];
__device__ int    g_cnt[N_NODES];
__device__ int    g_is64;

// ---------------- helpers ----------------

__device__ __forceinline__ int load_idx(const void* ei, int pos) {
    if (g_is64) return (int)((const long long*)ei)[pos];
    return ((const int*)ei)[pos];
}

__device__ __forceinline__ void cp_async16(void* smem_dst, const void* gsrc) {
    unsigned saddr = (unsigned)__cvta_generic_to_shared(smem_dst);
    asm volatile("cp.async.cg.shared.global [%0], [%1], 16;\n" ::"r"(saddr), "l"(gsrc));
}
#define CP_COMMIT() asm volatile("cp.async.commit_group;\n")
#define CP_WAIT1()  asm volatile("cp.async.wait_group 1;\n")

// m16n8k16 fp16 MMA, fp32 accum. A row-major, B col-major.
#define MMA_F16(C, A, B0, B1)                                                   \
    asm volatile(                                                               \
        "mma.sync.aligned.m16n8k16.row.col.f32.f16.f16.f32 "                    \
        "{%0,%1,%2,%3}, {%4,%5,%6,%7}, {%8,%9}, {%0,%1,%2,%3};\n"               \
        : "+f"((C)[0]), "+f"((C)[1]), "+f"((C)[2]), "+f"((C)[3])                \
        : "r"((A)[0]), "r"((A)[1]), "r"((A)[2]), "r"((A)[3]),                   \
          "r"((B0)), "r"((B1)))

__device__ __forceinline__ unsigned pack_h2(float a, float b) {
    unsigned u;
    asm("cvt.rn.f16x2.f32 %0, %2, %1;" : "=r"(u) : "f"(a), "f"(b));
    return u;   // lo half = a, hi half = b
}

// ---------------- K0: init + dtype sniff + w2 -> fp16 relayout ----------------

__global__ void k_init(const float* __restrict__ w2, const float* __restrict__ b2,
                       const void* __restrict__ ei) {
    if (blockIdx.x == 0 && threadIdx.x < 32) {
        const int* e32 = (const int*)ei;
        int nz = 0;
        for (int i = threadIdx.x; i < 2048; i += 32) nz |= e32[2 * i + 1];
        unsigned any = __ballot_sync(0xffffffffu, nz != 0);
        if (threadIdx.x == 0) g_is64 = (any == 0u) ? 1 : 0;
    }
    int i = blockIdx.x * blockDim.x + threadIdx.x;
    int stride = gridDim.x * blockDim.x;
    // dst idx = k*16384 + ih*8192 + o*64 + il ; src = w2[k][ (ih*64+il)*128 + o ]
    for (int idx = i; idx < W2HN; idx += stride) {
        int k  = idx >> 14;
        int rem = idx & 16383;
        int ih = rem >> 13;
        int o  = (rem >> 6) & 127;
        int il = rem & 63;
        int ii = ih * 64 + il;
        float v = (k < DD) ? w2[k * 16384 + ii * 128 + o] : b2[ii * 128 + o];
        g_w2h[idx] = __float2half_rn(v);
    }
    for (int idx = i; idx < N_NODES * DD; idx += stride) g_seg[idx] = 0.0f;
    for (int idx = i; idx < N_NODES; idx += stride) g_cnt[idx] = 0;
}

// ---------------- KA: edge MLP layer 1 + degree counts (R2-proven) ----------

#define SMEM_A ((64 * 132 + 128 * 132) * 4)

__global__ __launch_bounds__(256) void k_edge_mlp(
    const float* __restrict__ ea, const float* __restrict__ w1,
    const float* __restrict__ b1, const void* __restrict__ ei)
{
    extern __shared__ float smA[];
    float* eas = smA;             // [64][132]
    float* w1s = smA + 64 * 132;  // [128][132]
    const int tid = threadIdx.x;
    const int e0 = blockIdx.x * 64;

#pragma unroll
    for (int j = 0; j < 8; j++) {
        int idx = tid + j * 256;
        int r = idx >> 5, c4 = idx & 31;
        *(float4*)(eas + r * 132 + c4 * 4) =
            *(const float4*)(ea + (e0 + r) * DD + c4 * 4);
    }
#pragma unroll
    for (int j = 0; j < 16; j++) {
        int idx = tid + j * 256;
        int r = idx >> 5, c4 = idx & 31;
        *(float4*)(w1s + r * 132 + c4 * 4) = *(const float4*)(w1 + r * DD + c4 * 4);
    }
    __syncthreads();

    const int kq = tid & 15;
    const int eq = tid >> 4;
    float acc[4][8];
#pragma unroll
    for (int a = 0; a < 4; a++)
#pragma unroll
        for (int b = 0; b < 8; b++) acc[a][b] = 0.0f;

    for (int i = 0; i < DD; i++) {
        float4 wA = *(float4*)(w1s + i * 132 + kq * 8);
        float4 wB = *(float4*)(w1s + i * 132 + kq * 8 + 4);
#pragma unroll
        for (int je = 0; je < 4; je++) {
            float ev = eas[(eq * 4 + je) * 132 + i];
            acc[je][0] += ev * wA.x; acc[je][1] += ev * wA.y;
            acc[je][2] += ev * wA.z; acc[je][3] += ev * wA.w;
            acc[je][4] += ev * wB.x; acc[je][5] += ev * wB.y;
            acc[je][6] += ev * wB.z; acc[je][7] += ev * wB.w;
        }
    }

#pragma unroll
    for (int je = 0; je < 4; je++) {
        int e = e0 + eq * 4 + je;
#pragma unroll
        for (int jk = 0; jk < 8; jk++) {
            int k = kq * 8 + jk;
            g_h[e * DD + k] = fmaxf(acc[je][jk] + b1[k], 0.0f);
        }
    }
    if (tid < 64) {
        int dd = load_idx(ei, N_EDGES + e0 + tid);
        atomicAdd(&g_cnt[dd], 1);
    }
}

// ---------------- KB: fp16 mma.sync GEMM with on-the-fly A, fused scatter --
// CTA tile 128e x 128o. 8 warps: 4(E) x 2(O); warp 32e x 64o.
// 258 chunks = (k 0..127) x (ihalf 0/1) + 2 virtual b2 chunks (h==1), K=64 each.
// smem: Xs[128][132] f32, Hs[128][132] f32, Bs[2] fp16 tiles 128 o-rows x 144B.

#define B_ROW_BYTES 144
#define B_TILE_BYTES (128 * B_ROW_BYTES)   // 18432
#define XS_OFF  0
#define HS_OFF  (128 * 132 * 4)
#define BS_OFF  (2 * 128 * 132 * 4)
#define MISC_OFF (BS_OFF + 2 * B_TILE_BYTES)
#define SMEM_KB (MISC_OFF + 1024)

__global__ __launch_bounds__(256) void k_msg(
    const float* __restrict__ x, const void* __restrict__ ei)
{
    extern __shared__ char sm[];
    float* Xs  = (float*)(sm + XS_OFF);    // [128][132]
    float* Hs  = (float*)(sm + HS_OFF);    // [128][132]
    char*  BsC = sm + BS_OFF;              // [2][128][144B]
    int* s_src = (int*)(sm + MISC_OFF);
    int* s_dst = s_src + 128;

    const int tid = threadIdx.x;
    const int bid = blockIdx.x;
    const int eBase = bid * 128;

    if (tid < 128) {
        s_src[tid] = load_idx(ei, eBase + tid);
        s_dst[tid] = load_idx(ei, N_EDGES + eBase + tid);
    }
    __syncthreads();

    // gather x rows + h rows
#pragma unroll
    for (int j = 0; j < 16; j++) {
        int idx = tid + j * 256;
        int r = idx >> 5, c4 = idx & 31;
        *(float4*)(Xs + r * 132 + c4 * 4) =
            *(const float4*)(x + (size_t)s_src[r] * DD + c4 * 4);
        *(float4*)(Hs + r * 132 + c4 * 4) =
            *(const float4*)(g_h + (size_t)(eBase + r) * DD + c4 * 4);
    }

    const int start = 2 * bid;   // even => parity(cidx) == parity(t)

    // prefetch B for t=0,1 (16KB each: 128 rows x 8 x 16B)
#pragma unroll
    for (int pc = 0; pc < 2; pc++) {
        int c = start + pc; if (c >= 258) c -= 258;
        const __half* bsrc = g_w2h + (c >> 1) * 16384 + (c & 1) * 8192;
        char* bd = BsC + pc * B_TILE_BYTES;
#pragma unroll
        for (int j = 0; j < 4; j++) {
            int idx = tid + j * 256;          // 0..1023
            int r = idx >> 3, ch = idx & 7;
            cp_async16(bd + r * B_ROW_BYTES + ch * 16, bsrc + r * 64 + ch * 8);
        }
        CP_COMMIT();
    }
    __syncthreads();   // Xs/Hs visible

    const int w = tid >> 5, lane = tid & 31;
    const int wE = w >> 1, wO = w & 1;
    const int g = lane >> 2, tg = lane & 3;
    const int er0 = wE * 32;
    const int ob = wO * 64;

    const float* hr0 = Hs + (er0 + g) * 132;        // rows g, g+8, g+16, g+24
    const float* xbase0 = Xs + (er0 + g) * 132;

    float cacc[2][8][4];
#pragma unroll
    for (int a = 0; a < 2; a++)
#pragma unroll
        for (int b = 0; b < 8; b++)
#pragma unroll
            for (int q = 0; q < 4; q++) cacc[a][b][q] = 0.0f;

    const int NCH = 258;
    for (int t = 0; t < NCH; t++) {
        CP_WAIT1();
        __syncthreads();
        int cidx = start + t; if (cidx >= 258) cidx -= 258;
        const char* bsm = BsC + (t & 1) * B_TILE_BYTES;
        const int k = cidx >> 1;
        const int ibase = (cidx & 1) * 64;

        float h0, h1, h2, h3;
        if (k < 128) {
            h0 = hr0[k]; h1 = hr0[8 * 132 + k];
            h2 = hr0[16 * 132 + k]; h3 = hr0[24 * 132 + k];
        } else {
            h0 = h1 = h2 = h3 = 1.0f;   // b2 bilinear term
        }

#pragma unroll
        for (int s = 0; s < 4; s++) {
            const int iA = ibase + s * 16 + tg * 2;
            unsigned a0[4], a1[4];
            {
                const float* r0 = xbase0;                 // er0+g
                const float* r1 = xbase0 + 8 * 132;       // er0+8+g
                float2 p0 = *(const float2*)(r0 + iA);
                float2 p1 = *(const float2*)(r1 + iA);
                float2 p2 = *(const float2*)(r0 + iA + 8);
                float2 p3 = *(const float2*)(r1 + iA + 8);
                a0[0] = pack_h2(h0 * p0.x, h0 * p0.y);
                a0[1] = pack_h2(h1 * p1.x, h1 * p1.y);
                a0[2] = pack_h2(h0 * p2.x, h0 * p2.y);
                a0[3] = pack_h2(h1 * p3.x, h1 * p3.y);
            }
            {
                const float* r0 = xbase0 + 16 * 132;      // er0+16+g
                const float* r1 = xbase0 + 24 * 132;      // er0+24+g
                float2 p0 = *(const float2*)(r0 + iA);
                float2 p1 = *(const float2*)(r1 + iA);
                float2 p2 = *(const float2*)(r0 + iA + 8);
                float2 p3 = *(const float2*)(r1 + iA + 8);
                a1[0] = pack_h2(h2 * p0.x, h2 * p0.y);
                a1[1] = pack_h2(h3 * p1.x, h3 * p1.y);
                a1[2] = pack_h2(h2 * p2.x, h2 * p2.y);
                a1[3] = pack_h2(h3 * p3.x, h3 * p3.y);
            }
            // B: rows o = ob + nt*8 + g, halves at i_l = s*16 + tg*2 (+8)
            const char* bp = bsm + (ob + g) * B_ROW_BYTES + s * 32 + tg * 4;
#pragma unroll
            for (int nt = 0; nt < 8; nt++) {
                const char* bq = bp + nt * 8 * B_ROW_BYTES;
                unsigned B0 = *(const unsigned*)(bq);
                unsigned B1 = *(const unsigned*)(bq + 16);
                MMA_F16(cacc[0][nt], a0, B0, B1);
                MMA_F16(cacc[1][nt], a1, B0, B1);
            }
        }
        __syncthreads();   // all warps done reading Bs[t&1]
        if (t + 2 < NCH) {
            int c2 = start + t + 2; if (c2 >= 258) c2 -= 258;
            const __half* bsrc = g_w2h + (c2 >> 1) * 16384 + (c2 & 1) * 8192;
            char* bd = BsC + ((t + 2) & 1) * B_TILE_BYTES;
#pragma unroll
            for (int j = 0; j < 4; j++) {
                int idx = tid + j * 256;
                int r = idx >> 3, ch = idx & 7;
                cp_async16(bd + r * B_ROW_BYTES + ch * 16, bsrc + r * 64 + ch * 8);
            }
        }
        CP_COMMIT();   // empty tail groups keep wait arithmetic uniform
    }

    // fused scatter: atomicAdd into seg (C layout same as R2: rows g/g+8 per mt)
#pragma unroll
    for (int mt = 0; mt < 2; mt++) {
        int rl = er0 + mt * 16 + g;
        int d0 = s_dst[rl];
        int d1 = s_dst[rl + 8];
#pragma unroll
        for (int nt = 0; nt < 8; nt++) {
            int colb = ob + nt * 8 + tg * 2;
            atomicAdd(g_seg + (size_t)d0 * DD + colb,     cacc[mt][nt][0]);
            atomicAdd(g_seg + (size_t)d0 * DD + colb + 1, cacc[mt][nt][1]);
            atomicAdd(g_seg + (size_t)d1 * DD + colb,     cacc[mt][nt][2]);
            atomicAdd(g_seg + (size_t)d1 * DD + colb + 1, cacc[mt][nt][3]);
        }
    }
}

// ---------------- KC: mean + root transform + bias + gelu + residual ------

#define SMEM_C ((64 * 132 + 128 * 132) * 4)

__global__ __launch_bounds__(256) void k_final(
    const float* __restrict__ x, const float* __restrict__ root,
    const float* __restrict__ bias, float* __restrict__ out)
{
    extern __shared__ float smC[];
    float* xs = smC;
    float* rs = smC + 64 * 132;
    const int tid = threadIdx.x;
    const int n0 = blockIdx.x * 64;

#pragma unroll
    for (int j = 0; j < 8; j++) {
        int idx = tid + j * 256;
        int r = idx >> 5, c4 = idx & 31;
        float4 v = make_float4(0.f, 0.f, 0.f, 0.f);
        if (n0 + r < N_NODES) v = *(const float4*)(x + (n0 + r) * DD + c4 * 4);
        *(float4*)(xs + r * 132 + c4 * 4) = v;
    }
#pragma unroll
    for (int j = 0; j < 16; j++) {
        int idx = tid + j * 256;
        int r = idx >> 5, c4 = idx & 31;
        *(float4*)(rs + r * 132 + c4 * 4) = *(const float4*)(root + r * DD + c4 * 4);
    }
    __syncthreads();

    const int oq = tid & 15;
    const int nq = tid >> 4;
    float acc[4][8];
#pragma unroll
    for (int a = 0; a < 4; a++)
#pragma unroll
        for (int b = 0; b < 8; b++) acc[a][b] = 0.0f;

    for (int i = 0; i < DD; i++) {
        float4 rA = *(float4*)(rs + i * 132 + oq * 8);
        float4 rB = *(float4*)(rs + i * 132 + oq * 8 + 4);
#pragma unroll
        for (int jn = 0; jn < 4; jn++) {
            float xv = xs[(nq * 4 + jn) * 132 + i];
            acc[jn][0] += xv * rA.x; acc[jn][1] += xv * rA.y;
            acc[jn][2] += xv * rA.z; acc[jn][3] += xv * rA.w;
            acc[jn][4] += xv * rB.x; acc[jn][5] += xv * rB.y;
            acc[jn][6] += xv * rB.z; acc[jn][7] += xv * rB.w;
        }
    }

#pragma unroll
    for (int jn = 0; jn < 4; jn++) {
        int n = n0 + nq * 4 + jn;
        if (n < N_NODES) {
            float invc = 1.0f / fmaxf((float)g_cnt[n], 1.0f);
#pragma unroll
            for (int jo = 0; jo < 8; jo++) {
                int o = oq * 8 + jo;
                float v = acc[jn][jo] + bias[o] + g_seg[n * DD + o] * invc;
                float gl = 0.5f * v * (1.0f + erff(v * 0.70710678118654752f));
                out[n * DD + o] = xs[(nq * 4 + jn) * 132 + o] + gl;
            }
        }
    }
}

// ---------------- launch ----------------

extern "C" void kernel_launch(void* const* d_in, const int* in_sizes, int n_in,
                              void* d_out, int out_size) {
    const float* x    = (const float*)d_in[0];
    const void*  ei   = (const void*)d_in[1];
    const float* ea   = (const float*)d_in[2];
    const float* w1   = (const float*)d_in[3];
    const float* b1   = (const float*)d_in[4];
    const float* w2   = (const float*)d_in[5];
    const float* b2   = (const float*)d_in[6];
    const float* root = (const float*)d_in[7];
    const float* bias = (const float*)d_in[8];
    float*       out  = (float*)d_out;

    cudaFuncSetAttribute(k_edge_mlp, cudaFuncAttributeMaxDynamicSharedMemorySize, SMEM_A);
    cudaFuncSetAttribute(k_msg,      cudaFuncAttributeMaxDynamicSharedMemorySize, SMEM_KB);
    cudaFuncSetAttribute(k_final,    cudaFuncAttributeMaxDynamicSharedMemorySize, SMEM_C);

    k_init<<<2048, 256>>>(w2, b2, ei);
    k_edge_mlp<<<N_EDGES / 64, 256, SMEM_A>>>(ea, w1, b1, ei);
    k_msg<<<N_EDGES / 128, 256, SMEM_KB>>>(x, ei);
    k_final<<<(N_NODES + 63) / 64, 256, SMEM_C>>>(x, root, bias, out);
}

// round 9
// speedup vs baseline: 1.6307x; 1.1853x over previous
#include <cuda_runtime.h>
#include <cuda_fp16.h>
#include <cstdint>

// ---------------------------------------------------------------------------
// NNConv fused pipeline, fp16 mma.sync everywhere (tcgen05 rejected by
// harness's .target sm_103 ptxas).
//   K0: dtype-sniff, coalesced smem-transpose w2 -> fp16 [k][ih][o][il],
//       zero seg/cnt
//   KA: h = relu(ea @ w1 + b1) via m16n8k16 fp16 MMA (fp32 accum), + counts
//   KB: msg GEMM via m16n8k16 (unchanged from R8, proven 295us), fused scatter
//   KC: out = x + gelu(seg/cnt + x@root + bias), x@root via MMA
// ---------------------------------------------------------------------------

#define N_NODES 10000
#define N_EDGES 16384
#define DD      128
#define W2HN    ((DD + 1) * 16384)

__device__ float  g_h[N_EDGES * DD];   // [e][k] row-major fp32
__device__ __half g_w2h[W2HN];         // [k][ih][o][il]: k*16384+ih*8192+o*64+il
__device__ float  g_seg[N_NODES * DD];
__device__ int    g_cnt[N_NODES];
__device__ int    g_is64;

// ---------------- helpers ----------------

__device__ __forceinline__ int load_idx(const void* ei, int pos) {
    if (g_is64) return (int)((const long long*)ei)[pos];
    return ((const int*)ei)[pos];
}

__device__ __forceinline__ void cp_async16(void* smem_dst, const void* gsrc) {
    unsigned saddr = (unsigned)__cvta_generic_to_shared(smem_dst);
    asm volatile("cp.async.cg.shared.global [%0], [%1], 16;\n" ::"r"(saddr), "l"(gsrc));
}
#define CP_COMMIT() asm volatile("cp.async.commit_group;\n")
#define CP_WAIT1()  asm volatile("cp.async.wait_group 1;\n")

#define MMA_F16(C, A, B0, B1)                                                   \
    asm volatile(                                                               \
        "mma.sync.aligned.m16n8k16.row.col.f32.f16.f16.f32 "                    \
        "{%0,%1,%2,%3}, {%4,%5,%6,%7}, {%8,%9}, {%0,%1,%2,%3};\n"               \
        : "+f"((C)[0]), "+f"((C)[1]), "+f"((C)[2]), "+f"((C)[3])                \
        : "r"((A)[0]), "r"((A)[1]), "r"((A)[2]), "r"((A)[3]),                   \
          "r"((B0)), "r"((B1)))

__device__ __forceinline__ unsigned pack_h2(float a, float b) {
    unsigned u;
    asm("cvt.rn.f16x2.f32 %0, %2, %1;" : "=r"(u) : "f"(a), "f"(b));
    return u;   // lo = a, hi = b
}

// ---------------- K0: sniff + coalesced w2->fp16 transpose + zeroing --------
// blocks 0..128: transpose one k-slab each (k=128 handles b2).
// blocks 129..288: zero g_seg / g_cnt.

#define INIT_ZBLK 160

__global__ __launch_bounds__(256) void k_init(
    const float* __restrict__ w2, const float* __restrict__ b2,
    const void* __restrict__ ei)
{
    const int b = blockIdx.x;
    const int tid = threadIdx.x;

    if (b == 0 && tid < 32) {
        const int* e32 = (const int*)ei;
        int nz = 0;
        for (int i = tid; i < 2048; i += 32) nz |= e32[2 * i + 1];
        unsigned any = __ballot_sync(0xffffffffu, nz != 0);
        if (tid == 0) g_is64 = (any == 0u) ? 1 : 0;
    }

    if (b < 129) {
        __shared__ __half ts[128][136];   // [ii][o], padded
        const int k = b;
        const float* src = (k < DD) ? (w2 + (size_t)k * 16384) : b2;
        // coalesced read: rows ii, float4 over o
#pragma unroll
        for (int j = 0; j < 16; j++) {
            int idx = tid + j * 256;            // 0..4095 float4
            int ii = idx >> 5, o4 = (idx & 31) * 4;
            float4 v = *(const float4*)(src + ii * 128 + o4);
            __half2* d = (__half2*)&ts[ii][o4];
            d[0] = __floats2half2_rn(v.x, v.y);
            d[1] = __floats2half2_rn(v.z, v.w);
        }
        __syncthreads();
        // coalesced write: dst contiguous along il (8 halves = uint4)
#pragma unroll
        for (int j = 0; j < 8; j++) {
            int idx = tid + j * 256;            // 0..2047
            int ih = idx >> 10, rem = idx & 1023;
            int o = rem >> 3, il8 = (rem & 7) * 8;
            __half tmp[8];
#pragma unroll
            for (int q = 0; q < 8; q++) tmp[q] = ts[ih * 64 + il8 + q][o];
            *(uint4*)(g_w2h + (size_t)k * 16384 + ih * 8192 + o * 64 + il8) =
                *(uint4*)tmp;
        }
    } else {
        int i = (b - 129) * 256 + tid;
        int stride = INIT_ZBLK * 256;
        for (int idx = i; idx < N_NODES * DD; idx += stride) g_seg[idx] = 0.0f;
        for (int idx = i; idx < N_NODES; idx += stride) g_cnt[idx] = 0;
    }
}

// ---------------- KA: h = relu(ea @ w1 + b1) via fp16 MMA + counts ----------
// CTA: 128 edges x 128 k-outs. 8 warps 4(E)x2(O), warp 32e x 64k.
// smem: EAs fp16[128][136], W1T fp16[128][136] (transposed), b1s f32[128].

#define KA_EA_OFF  0
#define KA_W1_OFF  (128 * 136 * 2)
#define KA_B1_OFF  (2 * 128 * 136 * 2)
#define SMEM_KA    (KA_B1_OFF + 512 + 256)

__global__ __launch_bounds__(256) void k_edge_mlp(
    const float* __restrict__ ea, const float* __restrict__ w1,
    const float* __restrict__ b1, const void* __restrict__ ei)
{
    extern __shared__ char smA[];
    __half* EAs = (__half*)(smA + KA_EA_OFF);   // [e][i] pad 136
    __half* W1T = (__half*)(smA + KA_W1_OFF);   // [kq][i] pad 136
    float*  b1s = (float*)(smA + KA_B1_OFF);
    const int tid = threadIdx.x;
    const int e0 = blockIdx.x * 128;

    // ea -> fp16 smem (coalesced)
#pragma unroll
    for (int j = 0; j < 16; j++) {
        int idx = tid + j * 256;
        int r = idx >> 5, c4 = (idx & 31) * 4;
        float4 v = *(const float4*)(ea + (size_t)(e0 + r) * DD + c4);
        __half2* d = (__half2*)(EAs + r * 136 + c4);
        d[0] = __floats2half2_rn(v.x, v.y);
        d[1] = __floats2half2_rn(v.z, v.w);
    }
    // w1 -> transposed fp16 smem: W1T[kq][i] = w1[i][kq]
#pragma unroll
    for (int j = 0; j < 16; j++) {
        int idx = tid + j * 256;
        int i = idx >> 5, k4 = (idx & 31) * 4;
        float4 v = *(const float4*)(w1 + (size_t)i * DD + k4);
        W1T[(k4 + 0) * 136 + i] = __float2half_rn(v.x);
        W1T[(k4 + 1) * 136 + i] = __float2half_rn(v.y);
        W1T[(k4 + 2) * 136 + i] = __float2half_rn(v.z);
        W1T[(k4 + 3) * 136 + i] = __float2half_rn(v.w);
    }
    if (tid < 128) b1s[tid] = b1[tid];
    __syncthreads();

    const int w = tid >> 5, lane = tid & 31;
    const int wE = w >> 1, wO = w & 1;
    const int g = lane >> 2, tg = lane & 3;
    const int er0 = wE * 32;
    const int ob = wO * 64;

    const unsigned* EA32 = (const unsigned*)EAs;   // row stride 68 u32
    const unsigned* W132 = (const unsigned*)W1T;

    float cacc[2][8][4];
#pragma unroll
    for (int a = 0; a < 2; a++)
#pragma unroll
        for (int bq = 0; bq < 8; bq++)
#pragma unroll
            for (int q = 0; q < 4; q++) cacc[a][bq][q] = 0.0f;

#pragma unroll
    for (int c = 0; c < 8; c++) {       // i-chunks of 16
        const int colu = c * 8 + tg;
        unsigned a0[4], a1[4];
        a0[0] = EA32[(er0 + g) * 68 + colu];
        a0[1] = EA32[(er0 + 8 + g) * 68 + colu];
        a0[2] = EA32[(er0 + g) * 68 + colu + 4];
        a0[3] = EA32[(er0 + 8 + g) * 68 + colu + 4];
        a1[0] = EA32[(er0 + 16 + g) * 68 + colu];
        a1[1] = EA32[(er0 + 24 + g) * 68 + colu];
        a1[2] = EA32[(er0 + 16 + g) * 68 + colu + 4];
        a1[3] = EA32[(er0 + 24 + g) * 68 + colu + 4];
#pragma unroll
        for (int nt = 0; nt < 8; nt++) {
            const int ro = ob + nt * 8 + g;
            unsigned B0 = W132[ro * 68 + colu];
            unsigned B1 = W132[ro * 68 + colu + 4];
            MMA_F16(cacc[0][nt], a0, B0, B1);
            MMA_F16(cacc[1][nt], a1, B0, B1);
        }
    }

    // epilogue: relu(+b1), write g_h fp32
#pragma unroll
    for (int mt = 0; mt < 2; mt++) {
        int r0 = e0 + er0 + mt * 16 + g;
        int r1 = r0 + 8;
#pragma unroll
        for (int nt = 0; nt < 8; nt++) {
            int col = ob + nt * 8 + tg * 2;
            float ba = b1s[col], bb = b1s[col + 1];
            float2 v0 = make_float2(fmaxf(cacc[mt][nt][0] + ba, 0.0f),
                                    fmaxf(cacc[mt][nt][1] + bb, 0.0f));
            float2 v1 = make_float2(fmaxf(cacc[mt][nt][2] + ba, 0.0f),
                                    fmaxf(cacc[mt][nt][3] + bb, 0.0f));
            *(float2*)(g_h + (size_t)r0 * DD + col) = v0;
            *(float2*)(g_h + (size_t)r1 * DD + col) = v1;
        }
    }
    if (tid < 128) {
        int dd = load_idx(ei, N_EDGES + e0 + tid);
        atomicAdd(&g_cnt[dd], 1);
    }
}

// ---------------- KB: fp16 mma.sync GEMM (unchanged from R8, proven) -------

#define B_ROW_BYTES 144
#define B_TILE_BYTES (128 * B_ROW_BYTES)
#define XS_OFF  0
#define HS_OFF  (128 * 132 * 4)
#define BS_OFF  (2 * 128 * 132 * 4)
#define MISC_OFF (BS_OFF + 2 * B_TILE_BYTES)
#define SMEM_KB (MISC_OFF + 1024)

__global__ __launch_bounds__(256) void k_msg(
    const float* __restrict__ x, const void* __restrict__ ei)
{
    extern __shared__ char sm[];
    float* Xs  = (float*)(sm + XS_OFF);
    float* Hs  = (float*)(sm + HS_OFF);
    char*  BsC = sm + BS_OFF;
    int* s_src = (int*)(sm + MISC_OFF);
    int* s_dst = s_src + 128;

    const int tid = threadIdx.x;
    const int bid = blockIdx.x;
    const int eBase = bid * 128;

    if (tid < 128) {
        s_src[tid] = load_idx(ei, eBase + tid);
        s_dst[tid] = load_idx(ei, N_EDGES + eBase + tid);
    }
    __syncthreads();

#pragma unroll
    for (int j = 0; j < 16; j++) {
        int idx = tid + j * 256;
        int r = idx >> 5, c4 = idx & 31;
        *(float4*)(Xs + r * 132 + c4 * 4) =
            *(const float4*)(x + (size_t)s_src[r] * DD + c4 * 4);
        *(float4*)(Hs + r * 132 + c4 * 4) =
            *(const float4*)(g_h + (size_t)(eBase + r) * DD + c4 * 4);
    }

    const int start = 2 * bid;

#pragma unroll
    for (int pc = 0; pc < 2; pc++) {
        int c = start + pc; if (c >= 258) c -= 258;
        const __half* bsrc = g_w2h + (size_t)(c >> 1) * 16384 + (c & 1) * 8192;
        char* bd = BsC + pc * B_TILE_BYTES;
#pragma unroll
        for (int j = 0; j < 4; j++) {
            int idx = tid + j * 256;
            int r = idx >> 3, ch = idx & 7;
            cp_async16(bd + r * B_ROW_BYTES + ch * 16, bsrc + r * 64 + ch * 8);
        }
        CP_COMMIT();
    }
    __syncthreads();

    const int w = tid >> 5, lane = tid & 31;
    const int wE = w >> 1, wO = w & 1;
    const int g = lane >> 2, tg = lane & 3;
    const int er0 = wE * 32;
    const int ob = wO * 64;

    const float* hr0 = Hs + (er0 + g) * 132;
    const float* xbase0 = Xs + (er0 + g) * 132;

    float cacc[2][8][4];
#pragma unroll
    for (int a = 0; a < 2; a++)
#pragma unroll
        for (int b = 0; b < 8; b++)
#pragma unroll
            for (int q = 0; q < 4; q++) cacc[a][b][q] = 0.0f;

    const int NCH = 258;
    for (int t = 0; t < NCH; t++) {
        CP_WAIT1();
        __syncthreads();
        int cidx = start + t; if (cidx >= 258) cidx -= 258;
        const char* bsm = BsC + (t & 1) * B_TILE_BYTES;
        const int k = cidx >> 1;
        const int ibase = (cidx & 1) * 64;

        float h0, h1, h2, h3;
        if (k < 128) {
            h0 = hr0[k]; h1 = hr0[8 * 132 + k];
            h2 = hr0[16 * 132 + k]; h3 = hr0[24 * 132 + k];
        } else {
            h0 = h1 = h2 = h3 = 1.0f;
        }

#pragma unroll
        for (int s = 0; s < 4; s++) {
            const int iA = ibase + s * 16 + tg * 2;
            unsigned a0[4], a1[4];
            {
                const float* r0 = xbase0;
                const float* r1 = xbase0 + 8 * 132;
                float2 p0 = *(const float2*)(r0 + iA);
                float2 p1 = *(const float2*)(r1 + iA);
                float2 p2 = *(const float2*)(r0 + iA + 8);
                float2 p3 = *(const float2*)(r1 + iA + 8);
                a0[0] = pack_h2(h0 * p0.x, h0 * p0.y);
                a0[1] = pack_h2(h1 * p1.x, h1 * p1.y);
                a0[2] = pack_h2(h0 * p2.x, h0 * p2.y);
                a0[3] = pack_h2(h1 * p3.x, h1 * p3.y);
            }
            {
                const float* r0 = xbase0 + 16 * 132;
                const float* r1 = xbase0 + 24 * 132;
                float2 p0 = *(const float2*)(r0 + iA);
                float2 p1 = *(const float2*)(r1 + iA);
                float2 p2 = *(const float2*)(r0 + iA + 8);
                float2 p3 = *(const float2*)(r1 + iA + 8);
                a1[0] = pack_h2(h2 * p0.x, h2 * p0.y);
                a1[1] = pack_h2(h3 * p1.x, h3 * p1.y);
                a1[2] = pack_h2(h2 * p2.x, h2 * p2.y);
                a1[3] = pack_h2(h3 * p3.x, h3 * p3.y);
            }
            const char* bp = bsm + (ob + g) * B_ROW_BYTES + s * 32 + tg * 4;
#pragma unroll
            for (int nt = 0; nt < 8; nt++) {
                const char* bq = bp + nt * 8 * B_ROW_BYTES;
                unsigned B0 = *(const unsigned*)(bq);
                unsigned B1 = *(const unsigned*)(bq + 16);
                MMA_F16(cacc[0][nt], a0, B0, B1);
                MMA_F16(cacc[1][nt], a1, B0, B1);
            }
        }
        __syncthreads();
        if (t + 2 < NCH) {
            int c2 = start + t + 2; if (c2 >= 258) c2 -= 258;
            const __half* bsrc = g_w2h + (size_t)(c2 >> 1) * 16384 + (c2 & 1) * 8192;
            char* bd = BsC + ((t + 2) & 1) * B_TILE_BYTES;
#pragma unroll
            for (int j = 0; j < 4; j++) {
                int idx = tid + j * 256;
                int r = idx >> 3, ch = idx & 7;
                cp_async16(bd + r * B_ROW_BYTES + ch * 16, bsrc + r * 64 + ch * 8);
            }
        }
        CP_COMMIT();
    }

#pragma unroll
    for (int mt = 0; mt < 2; mt++) {
        int rl = er0 + mt * 16 + g;
        int d0 = s_dst[rl];
        int d1 = s_dst[rl + 8];
#pragma unroll
        for (int nt = 0; nt < 8; nt++) {
            int colb = ob + nt * 8 + tg * 2;
            atomicAdd(g_seg + (size_t)d0 * DD + colb,     cacc[mt][nt][0]);
            atomicAdd(g_seg + (size_t)d0 * DD + colb + 1, cacc[mt][nt][1]);
            atomicAdd(g_seg + (size_t)d1 * DD + colb,     cacc[mt][nt][2]);
            atomicAdd(g_seg + (size_t)d1 * DD + colb + 1, cacc[mt][nt][3]);
        }
    }
}

// ---------------- KC: x@root via MMA + mean + bias + gelu + residual -------
// CTA: 128 nodes x 128 outs. smem: Xf f32[128][132], XH fp16[128][136],
// RT fp16[128][136], biass f32[128].

#define KC_XF_OFF 0
#define KC_XH_OFF (128 * 132 * 4)
#define KC_RT_OFF (KC_XH_OFF + 128 * 136 * 2)
#define KC_BI_OFF (KC_RT_OFF + 128 * 136 * 2)
#define SMEM_KC   (KC_BI_OFF + 512 + 256)

__global__ __launch_bounds__(256) void k_final(
    const float* __restrict__ x, const float* __restrict__ root,
    const float* __restrict__ bias, float* __restrict__ out)
{
    extern __shared__ char smC[];
    float*  Xf = (float*)(smC + KC_XF_OFF);    // [n][i] pad 132
    __half* XH = (__half*)(smC + KC_XH_OFF);   // [n][i] pad 136
    __half* RT = (__half*)(smC + KC_RT_OFF);   // [o][i] pad 136 (transposed)
    float*  bs = (float*)(smC + KC_BI_OFF);
    const int tid = threadIdx.x;
    const int n0 = blockIdx.x * 128;

#pragma unroll
    for (int j = 0; j < 16; j++) {
        int idx = tid + j * 256;
        int r = idx >> 5, c4 = (idx & 31) * 4;
        float4 v = make_float4(0.f, 0.f, 0.f, 0.f);
        if (n0 + r < N_NODES) v = *(const float4*)(x + (size_t)(n0 + r) * DD + c4);
        *(float4*)(Xf + r * 132 + c4) = v;
        __half2* d = (__half2*)(XH + r * 136 + c4);
        d[0] = __floats2half2_rn(v.x, v.y);
        d[1] = __floats2half2_rn(v.z, v.w);
    }
#pragma unroll
    for (int j = 0; j < 16; j++) {
        int idx = tid + j * 256;
        int i = idx >> 5, o4 = (idx & 31) * 4;
        float4 v = *(const float4*)(root + (size_t)i * DD + o4);
        RT[(o4 + 0) * 136 + i] = __float2half_rn(v.x);
        RT[(o4 + 1) * 136 + i] = __float2half_rn(v.y);
        RT[(o4 + 2) * 136 + i] = __float2half_rn(v.z);
        RT[(o4 + 3) * 136 + i] = __float2half_rn(v.w);
    }
    if (tid < 128) bs[tid] = bias[tid];
    __syncthreads();

    const int w = tid >> 5, lane = tid & 31;
    const int wE = w >> 1, wO = w & 1;
    const int g = lane >> 2, tg = lane & 3;
    const int er0 = wE * 32;
    const int ob = wO * 64;

    const unsigned* XH32 = (const unsigned*)XH;
    const unsigned* RT32 = (const unsigned*)RT;

    float cacc[2][8][4];
#pragma unroll
    for (int a = 0; a < 2; a++)
#pragma unroll
        for (int bq = 0; bq < 8; bq++)
#pragma unroll
            for (int q = 0; q < 4; q++) cacc[a][bq][q] = 0.0f;

#pragma unroll
    for (int c = 0; c < 8; c++) {
        const int colu = c * 8 + tg;
        unsigned a0[4], a1[4];
        a0[0] = XH32[(er0 + g) * 68 + colu];
        a0[1] = XH32[(er0 + 8 + g) * 68 + colu];
        a0[2] = XH32[(er0 + g) * 68 + colu + 4];
        a0[3] = XH32[(er0 + 8 + g) * 68 + colu + 4];
        a1[0] = XH32[(er0 + 16 + g) * 68 + colu];
        a1[1] = XH32[(er0 + 24 + g) * 68 + colu];
        a1[2] = XH32[(er0 + 16 + g) * 68 + colu + 4];
        a1[3] = XH32[(er0 + 24 + g) * 68 + colu + 4];
#pragma unroll
        for (int nt = 0; nt < 8; nt++) {
            const int ro = ob + nt * 8 + g;
            unsigned B0 = RT32[ro * 68 + colu];
            unsigned B1 = RT32[ro * 68 + colu + 4];
            MMA_F16(cacc[0][nt], a0, B0, B1);
            MMA_F16(cacc[1][nt], a1, B0, B1);
        }
    }

    // epilogue
#pragma unroll
    for (int mt = 0; mt < 2; mt++) {
        int rl0 = er0 + mt * 16 + g;
        int rl1 = rl0 + 8;
        int r0 = n0 + rl0, r1 = n0 + rl1;
        float invc0 = 0.f, invc1 = 0.f;
        if (r0 < N_NODES) invc0 = 1.0f / fmaxf((float)g_cnt[r0], 1.0f);
        if (r1 < N_NODES) invc1 = 1.0f / fmaxf((float)g_cnt[r1], 1.0f);
#pragma unroll
        for (int nt = 0; nt < 8; nt++) {
            int col = ob + nt * 8 + tg * 2;
            float ba = bs[col], bb = bs[col + 1];
            if (r0 < N_NODES) {
                float2 sg = *(const float2*)(g_seg + (size_t)r0 * DD + col);
                float va = cacc[mt][nt][0] + ba + sg.x * invc0;
                float vb = cacc[mt][nt][1] + bb + sg.y * invc0;
                float ga = 0.5f * va * (1.0f + erff(va * 0.70710678118654752f));
                float gb = 0.5f * vb * (1.0f + erff(vb * 0.70710678118654752f));
                float2 o2;
                o2.x = Xf[rl0 * 132 + col] + ga;
                o2.y = Xf[rl0 * 132 + col + 1] + gb;
                *(float2*)(out + (size_t)r0 * DD + col) = o2;
            }
            if (r1 < N_NODES) {
                float2 sg = *(const float2*)(g_seg + (size_t)r1 * DD + col);
                float va = cacc[mt][nt][2] + ba + sg.x * invc1;
                float vb = cacc[mt][nt][3] + bb + sg.y * invc1;
                float ga = 0.5f * va * (1.0f + erff(va * 0.70710678118654752f));
                float gb = 0.5f * vb * (1.0f + erff(vb * 0.70710678118654752f));
                float2 o2;
                o2.x = Xf[rl1 * 132 + col] + ga;
                o2.y = Xf[rl1 * 132 + col + 1] + gb;
                *(float2*)(out + (size_t)r1 * DD + col) = o2;
            }
        }
    }
}

// ---------------- launch ----------------

extern "C" void kernel_launch(void* const* d_in, const int* in_sizes, int n_in,
                              void* d_out, int out_size) {
    const float* x    = (const float*)d_in[0];
    const void*  ei   = (const void*)d_in[1];
    const float* ea   = (const float*)d_in[2];
    const float* w1   = (const float*)d_in[3];
    const float* b1   = (const float*)d_in[4];
    const float* w2   = (const float*)d_in[5];
    const float* b2   = (const float*)d_in[6];
    const float* root = (const float*)d_in[7];
    const float* bias = (const float*)d_in[8];
    float*       out  = (float*)d_out;

    cudaFuncSetAttribute(k_edge_mlp, cudaFuncAttributeMaxDynamicSharedMemorySize, SMEM_KA);
    cudaFuncSetAttribute(k_msg,      cudaFuncAttributeMaxDynamicSharedMemorySize, SMEM_KB);
    cudaFuncSetAttribute(k_final,    cudaFuncAttributeMaxDynamicSharedMemorySize, SMEM_KC);

    k_init<<<129 + INIT_ZBLK, 256>>>(w2, b2, ei);
    k_edge_mlp<<<N_EDGES / 128, 256, SMEM_KA>>>(ea, w1, b1, ei);
    k_msg<<<N_EDGES / 128, 256, SMEM_KB>>>(x, ei);
    k_final<<<(N_NODES + 127) / 128, 256, SMEM_KC>>>(x, root, bias, out);
}